// round 2
// baseline (speedup 1.0000x reference)
#include <cuda_runtime.h>

// SupConLoss, N=8192 rows, D=128 features, 1000 classes, T=0.1.
// sim matrix (8192^2) never materialized; symmetry halves the GEMM work.
// Labels dtype (int64 vs int32) detected at runtime on device.

static constexpr int NN   = 8192;
static constexpr int DD   = 128;
static constexpr int TILE = 64;
static constexpr int NB   = NN / TILE;   // 128

__device__ float g_feat[NN * DD];   // L2-normalized features
__device__ float g_sumexp[NN];      // sum_{j != i} exp(sim_ij)
__device__ float g_possum[NN];      // sum_{j != i, label match} sim_ij
__device__ int   g_lab[NN];
__device__ int   g_hist[1024];
__device__ int   g_is64;

// ---------------------------------------------------------------------------
__global__ void init_kernel(float* out) {
    int gid = blockIdx.x * blockDim.x + threadIdx.x;
    if (gid < NN)   { g_sumexp[gid] = 0.0f; g_possum[gid] = 0.0f; }
    if (gid < 1024) g_hist[gid] = 0;
    if (gid == 0)   out[0] = 0.0f;
}

// Detect whether the label buffer is int64 (little-endian: every odd int32
// word of the first NN words is a zero high-half) or plain int32.
__global__ void detect_kernel(const int* __restrict__ labs) {
    __shared__ int red[256];
    int tid = threadIdx.x;
    int nz = 0;
    for (int i = tid; i < NN / 2; i += 256) nz |= labs[2 * i + 1];
    red[tid] = nz;
    __syncthreads();
    for (int s = 128; s > 0; s >>= 1) {
        if (tid < s) red[tid] |= red[tid + s];
        __syncthreads();
    }
    if (tid == 0) g_is64 = (red[0] == 0) ? 1 : 0;
}

// Normalize rows (one warp per row) + label histogram.
__global__ void prep_kernel(const float* __restrict__ feats,
                            const void* __restrict__ labels) {
    int row  = blockIdx.x * 8 + (threadIdx.x >> 5);
    int lane = threadIdx.x & 31;
    float4 v = reinterpret_cast<const float4*>(feats)[row * 32 + lane];
    float ss = v.x * v.x + v.y * v.y + v.z * v.z + v.w * v.w;
    #pragma unroll
    for (int o = 16; o > 0; o >>= 1) ss += __shfl_xor_sync(0xffffffffu, ss, o);
    float sc = 1.0f / sqrtf(ss);
    float4 w = make_float4(v.x * sc, v.y * sc, v.z * sc, v.w * sc);
    reinterpret_cast<float4*>(g_feat)[row * 32 + lane] = w;
    if (lane == 0) {
        int lab = g_is64 ? (int)((const long long*)labels)[row]
                         : ((const int*)labels)[row];
        g_lab[row] = lab;
        atomicAdd(&g_hist[lab & 1023], 1);
    }
}

// ---------------------------------------------------------------------------
// Main fused GEMM + epilogue. Tiles stored K-transposed in smem with XOR
// swizzle: element (k, r) lives at  k*64 + 4*((r>>2) ^ (k&15)) + (r&3).
__global__ void __launch_bounds__(256)
main_kernel() {
    int bi = blockIdx.y, bj = blockIdx.x;
    if (bj < bi) return;

    __shared__ __align__(16) float As[DD * TILE];
    __shared__ __align__(16) float Bs[DD * TILE];
    __shared__ float s_ce[TILE], s_cp[TILE];
    __shared__ int   s_li[TILE], s_lj[TILE];

    int tid = threadIdx.x;
    int tx = tid & 15, ty = tid >> 4;
    bool diag = (bi == bj);

    if (tid < TILE) {
        s_li[tid] = g_lab[bi * TILE + tid];
        s_lj[tid] = g_lab[bj * TILE + tid];
        s_ce[tid] = 0.0f;
        s_cp[tid] = 0.0f;
    }

    const float* Ag = g_feat + bi * TILE * DD;
    const float* Bg = g_feat + bj * TILE * DD;
    #pragma unroll
    for (int it = 0; it < 32; it++) {
        int idx = it * 256 + tid;
        int k = idx & 127;
        int r = idx >> 7;
        int sw = k * 64 + ((((r >> 2) ^ (k & 15)) << 2) | (r & 3));
        As[sw] = Ag[r * DD + k];
        Bs[sw] = Bg[r * DD + k];
    }
    __syncthreads();

    float acc[4][4];
    #pragma unroll
    for (int m = 0; m < 4; m++)
        #pragma unroll
        for (int n = 0; n < 4; n++) acc[m][n] = 0.0f;

    for (int k0 = 0; k0 < DD; k0 += 16) {
        #pragma unroll
        for (int kk = 0; kk < 16; kk++) {
            int kb = (k0 + kk) * 64;
            float4 a = *reinterpret_cast<const float4*>(&As[kb + ((ty ^ kk) << 2)]);
            float4 b = *reinterpret_cast<const float4*>(&Bs[kb + ((tx ^ kk) << 2)]);
            acc[0][0] += a.x * b.x; acc[0][1] += a.x * b.y; acc[0][2] += a.x * b.z; acc[0][3] += a.x * b.w;
            acc[1][0] += a.y * b.x; acc[1][1] += a.y * b.y; acc[1][2] += a.y * b.z; acc[1][3] += a.y * b.w;
            acc[2][0] += a.z * b.x; acc[2][1] += a.z * b.y; acc[2][2] += a.z * b.z; acc[2][3] += a.z * b.w;
            acc[3][0] += a.w * b.x; acc[3][1] += a.w * b.y; acc[3][2] += a.w * b.z; acc[3][3] += a.w * b.w;
        }
    }

    // Fused epilogue: sim = acc * 10 (1/T).
    float re[4] = {0, 0, 0, 0}, rp[4] = {0, 0, 0, 0};
    float ce[4] = {0, 0, 0, 0}, cp[4] = {0, 0, 0, 0};
    #pragma unroll
    for (int m = 0; m < 4; m++) {
        int gi = 4 * ty + m;
        int li = s_li[gi];
        #pragma unroll
        for (int n = 0; n < 4; n++) {
            int gj = 4 * tx + n;
            float s = acc[m][n] * 10.0f;
            bool self = diag && (gi == gj);
            float e = self ? 0.0f : __expf(s);
            re[m] += e;
            ce[n] += e;
            if (!self && li == s_lj[gj]) { rp[m] += s; cp[n] += s; }
        }
    }

    #pragma unroll
    for (int m = 0; m < 4; m++) {
        re[m] += __shfl_xor_sync(0xffffffffu, re[m], 1);
        re[m] += __shfl_xor_sync(0xffffffffu, re[m], 2);
        re[m] += __shfl_xor_sync(0xffffffffu, re[m], 4);
        re[m] += __shfl_xor_sync(0xffffffffu, re[m], 8);
        rp[m] += __shfl_xor_sync(0xffffffffu, rp[m], 1);
        rp[m] += __shfl_xor_sync(0xffffffffu, rp[m], 2);
        rp[m] += __shfl_xor_sync(0xffffffffu, rp[m], 4);
        rp[m] += __shfl_xor_sync(0xffffffffu, rp[m], 8);
        ce[m] += __shfl_xor_sync(0xffffffffu, ce[m], 16);
        cp[m] += __shfl_xor_sync(0xffffffffu, cp[m], 16);
    }

    if (tx == 0) {
        #pragma unroll
        for (int m = 0; m < 4; m++) {
            atomicAdd(&g_sumexp[bi * TILE + 4 * ty + m], re[m]);
            atomicAdd(&g_possum[bi * TILE + 4 * ty + m], rp[m]);
        }
    }
    if (!diag && (tid & 16) == 0) {
        #pragma unroll
        for (int n = 0; n < 4; n++) {
            atomicAdd(&s_ce[4 * tx + n], ce[n]);
            atomicAdd(&s_cp[4 * tx + n], cp[n]);
        }
    }
    __syncthreads();
    if (!diag && tid < TILE) {
        atomicAdd(&g_sumexp[bj * TILE + tid], s_ce[tid]);
        atomicAdd(&g_possum[bj * TILE + tid], s_cp[tid]);
    }
}

// ---------------------------------------------------------------------------
__global__ void finish_kernel(float* out) {
    __shared__ float red[256];
    int tid = threadIdx.x;
    float sum = 0.0f;
    for (int r = tid; r < NN; r += 256) {
        float L   = logf(g_sumexp[r] + 1e-9f);
        int   cnt = g_hist[g_lab[r] & 1023] - 1;
        float c   = (cnt > 0) ? (g_possum[r] - (float)cnt * L) / (float)cnt : 0.0f;
        sum += c;
    }
    red[tid] = sum;
    __syncthreads();
    for (int s = 128; s > 0; s >>= 1) {
        if (tid < s) red[tid] += red[tid + s];
        __syncthreads();
    }
    if (tid == 0) out[0] = -red[0] / (float)NN;
}

// ---------------------------------------------------------------------------
extern "C" void kernel_launch(void* const* d_in, const int* in_sizes, int n_in,
                              void* d_out, int out_size) {
    const float* feats = (const float*)d_in[0];
    const void*  labels = d_in[1];
    float* out = (float*)d_out;

    init_kernel<<<32, 256>>>(out);
    detect_kernel<<<1, 256>>>((const int*)labels);
    prep_kernel<<<NN / 8, 256>>>(feats, labels);
    main_kernel<<<dim3(NB, NB), 256>>>();
    finish_kernel<<<1, 256>>>(out);
}

// round 8
// speedup vs baseline: 2.8256x; 2.8256x over previous
#include <cuda_runtime.h>
#include <cuda_bf16.h>
#include <cstdint>

// SupConLoss N=8192, D=128, T=0.1.
// GEMM on tensor cores via arch-portable mma.sync (bf16, m16n8k16) — the
// harness toolchain targets sm_103 (no 'a'), so tcgen05 is unavailable.
// Row-only fused epilogue; sim matrix never materialized.

static constexpr int NN = 8192;
static constexpr int DD = 128;
static constexpr int TM = 128;            // tile dim (M and N)
static constexpr int NT = NN / TM;        // 64 tiles per axis
static constexpr int BJ_PER = 8;          // bj tiles per CTA
static constexpr int PARTS = NT / BJ_PER; // 8 -> grid 512

__device__ __align__(16) __nv_bfloat16 g_featbf[NN * DD];
__device__ float g_sumexp[NN];
__device__ float g_possum[NN];
__device__ int   g_lab[NN];
__device__ int   g_hist[1024];
__device__ int   g_is64;

// ---------------- PTX helpers (all base-target, no 'a' features) ------------
__device__ __forceinline__ uint32_t smem_u32(const void* p) {
    uint32_t a;
    asm("{ .reg .u64 t; cvta.to.shared.u64 t, %1; cvt.u32.u64 %0, t; }"
        : "=r"(a) : "l"(p));
    return a;
}

#define LDSM4(r0, r1, r2, r3, addr) \
    asm volatile("ldmatrix.sync.aligned.m8n8.x4.shared.b16 {%0,%1,%2,%3}, [%4];" \
        : "=r"(r0), "=r"(r1), "=r"(r2), "=r"(r3) : "r"(addr))

#define MMA16816(d, a, b) \
    asm volatile("mma.sync.aligned.m16n8k16.row.col.f32.bf16.bf16.f32 " \
        "{%0,%1,%2,%3}, {%4,%5,%6,%7}, {%8,%9}, {%0,%1,%2,%3};" \
        : "+f"((d)[0]), "+f"((d)[1]), "+f"((d)[2]), "+f"((d)[3]) \
        : "r"((a)[0]), "r"((a)[1]), "r"((a)[2]), "r"((a)[3]), \
          "r"((b)[0]), "r"((b)[1]))

#define CP_ASYNC16(sdst, gsrc) \
    asm volatile("cp.async.cg.shared.global [%0], [%1], 16;" \
        :: "r"(sdst), "l"(gsrc) : "memory")
#define CP_COMMIT()  asm volatile("cp.async.commit_group;" ::: "memory")
#define CP_WAIT0()   asm volatile("cp.async.wait_group 0;" ::: "memory")
#define CP_WAIT1()   asm volatile("cp.async.wait_group 1;" ::: "memory")

// ---------------------------------------------------------------------------
__global__ void init_kernel(float* out) {
    int gid = blockIdx.x * blockDim.x + threadIdx.x;
    if (gid < NN)   { g_sumexp[gid] = 0.0f; g_possum[gid] = 0.0f; }
    if (gid < 1024) g_hist[gid] = 0;
    if (gid == 0)   out[0] = 0.0f;
}

__global__ void detect_kernel(const int* __restrict__ labs) {
    __shared__ int red[256];
    int tid = threadIdx.x;
    int nz = 0;
    for (int i = tid; i < NN / 2; i += 256) nz |= labs[2 * i + 1];
    red[tid] = nz;
    __syncthreads();
    for (int s = 128; s > 0; s >>= 1) {
        if (tid < s) red[tid] |= red[tid + s];
        __syncthreads();
    }
    if (tid == 0) g_is64 = (red[0] == 0) ? 1 : 0;
}

// Normalize rows, convert to bf16, label histogram.
__global__ void prep_kernel(const float* __restrict__ feats,
                            const void* __restrict__ labels) {
    int row  = blockIdx.x * 8 + (threadIdx.x >> 5);
    int lane = threadIdx.x & 31;
    float4 v = reinterpret_cast<const float4*>(feats)[row * 32 + lane];
    float ss = v.x * v.x + v.y * v.y + v.z * v.z + v.w * v.w;
    #pragma unroll
    for (int o = 16; o > 0; o >>= 1) ss += __shfl_xor_sync(0xffffffffu, ss, o);
    float sc = 1.0f / sqrtf(ss);
    __nv_bfloat162 p0 = __floats2bfloat162_rn(v.x * sc, v.y * sc);
    __nv_bfloat162 p1 = __floats2bfloat162_rn(v.z * sc, v.w * sc);
    uint2 u;
    u.x = *reinterpret_cast<uint32_t*>(&p0);
    u.y = *reinterpret_cast<uint32_t*>(&p1);
    reinterpret_cast<uint2*>(g_featbf)[row * 32 + lane] = u;
    if (lane == 0) {
        int lab = g_is64 ? (int)((const long long*)labels)[row]
                         : ((const int*)labels)[row];
        g_lab[row] = lab;
        atomicAdd(&g_hist[lab & 1023], 1);
    }
}

// ---------------------------------------------------------------------------
// SMEM: A tile 32KB | B tiles 2x32KB | col labels 2x512B.
// Tile layout: 128 rows x 256B (K-major), 16B chunk XOR-swizzled by (row&7):
//   byte(row, chunk) = row*256 + ((chunk ^ (row&7)) << 4)
// -> ldmatrix (8 rows/phase, distinct row&7) is bank-conflict free.
static constexpr int SM_A   = 0;
static constexpr int SM_B0  = 32768;
static constexpr int SM_B1  = 65536;
static constexpr int SM_LJ0 = 98304;
static constexpr int SM_LJ1 = 98816;
static constexpr int SM_TOT = 99328;

__device__ __forceinline__ void cp_tile(uint32_t sdst,
                                        const __nv_bfloat16* gsrc, int tid) {
    #pragma unroll
    for (int i = 0; i < 16; i++) {
        int e   = i * 128 + tid;        // 2048 x 16B, coalesced
        int row = e >> 4;
        int ch  = e & 15;
        uint32_t off = row * 256 + (((ch ^ (row & 7))) << 4);
        CP_ASYNC16(sdst + off, (const char*)gsrc + (size_t)e * 16);
    }
}

__global__ void __launch_bounds__(128)
main_kernel() {
    extern __shared__ char smem[];
    uint32_t sb = smem_u32(smem);
    int tid  = threadIdx.x;
    int wid  = tid >> 5, lane = tid & 31;
    int sub  = lane & 7, g = lane >> 3;

    int bi   = blockIdx.x >> 3;
    int part = blockIdx.x & 7;
    int bj0  = part * BJ_PER;

    // Prefetch A, B0, labels0 (group 0)
    cp_tile(sb + SM_A,  g_featbf + (size_t)bi  * TM * DD, tid);
    cp_tile(sb + SM_B0, g_featbf + (size_t)bj0 * TM * DD, tid);
    if (tid < 32) CP_ASYNC16(sb + SM_LJ0 + tid * 16,
                             (const char*)(g_lab + bj0 * TM) + tid * 16);
    CP_COMMIT();

    // Per-lane row labels (4 rows owned per lane)
    int li[2][2];
    #pragma unroll
    for (int mt = 0; mt < 2; mt++)
        #pragma unroll
        for (int h = 0; h < 2; h++)
            li[mt][h] = g_lab[bi * TM + wid * 32 + mt * 16 + h * 8 + (lane >> 2)];

    // ldmatrix lane-group bases
    int arow = wid * 32 + (g & 1) * 8 + sub;   // + mt*16
    int brow = (g >> 1) * 8 + sub;             // + nc*64 + p*16
    int akx  = (g >> 1);                       // k-chunk lsb for A
    int bkx  = (g & 1);                        // k-chunk lsb for B

    float re[2][2] = {{0, 0}, {0, 0}};
    float rp[2][2] = {{0, 0}, {0, 0}};

    for (int it = 0; it < BJ_PER; it++) {
        int bj = bj0 + it;
        if (it + 1 < BJ_PER) {
            uint32_t nb = (it & 1) ? SM_B0 : SM_B1;
            uint32_t nl = (it & 1) ? SM_LJ0 : SM_LJ1;
            cp_tile(sb + nb, g_featbf + (size_t)(bj + 1) * TM * DD, tid);
            if (tid < 32) CP_ASYNC16(sb + nl + tid * 16,
                                     (const char*)(g_lab + (bj + 1) * TM) + tid * 16);
            CP_COMMIT();
            CP_WAIT1();
        } else {
            CP_WAIT0();
        }
        __syncthreads();

        uint32_t SB  = sb + ((it & 1) ? SM_B1 : SM_B0);
        const int* s_lj = reinterpret_cast<const int*>(
            smem + ((it & 1) ? SM_LJ1 : SM_LJ0));
        bool diag = (bj == bi);

        #pragma unroll
        for (int nc = 0; nc < 2; nc++) {
            float acc[2][8][4];
            #pragma unroll
            for (int mt = 0; mt < 2; mt++)
                #pragma unroll
                for (int nt = 0; nt < 8; nt++)
                    #pragma unroll
                    for (int q = 0; q < 4; q++) acc[mt][nt][q] = 0.0f;

            #pragma unroll
            for (int k = 0; k < 8; k++) {
                uint32_t a[2][4];
                #pragma unroll
                for (int mt = 0; mt < 2; mt++) {
                    uint32_t addr = sb + SM_A + (arow + mt * 16) * 256
                                  + (((k * 2 + akx) ^ sub) << 4);
                    LDSM4(a[mt][0], a[mt][1], a[mt][2], a[mt][3], addr);
                }
                uint32_t b[8][2];
                #pragma unroll
                for (int p = 0; p < 4; p++) {
                    uint32_t addr = SB + (nc * 64 + p * 16 + brow) * 256
                                  + (((k * 2 + bkx) ^ sub) << 4);
                    LDSM4(b[2 * p][0], b[2 * p][1], b[2 * p + 1][0], b[2 * p + 1][1], addr);
                }
                #pragma unroll
                for (int mt = 0; mt < 2; mt++)
                    #pragma unroll
                    for (int nt = 0; nt < 8; nt++)
                        MMA16816(acc[mt][nt], a[mt], b[nt]);
            }

            // Fused epilogue on register fragments.
            #pragma unroll
            for (int nt = 0; nt < 8; nt++) {
                int c0  = nc * 64 + nt * 8 + 2 * (lane & 3);
                int lj0 = s_lj[c0], lj1 = s_lj[c0 + 1];
                #pragma unroll
                for (int mt = 0; mt < 2; mt++) {
                    int r0 = wid * 32 + mt * 16 + (lane >> 2);
                    #pragma unroll
                    for (int q = 0; q < 4; q++) {
                        int   row = r0 + (q >> 1) * 8;
                        int   col = c0 + (q & 1);
                        int   lj  = (q & 1) ? lj1 : lj0;
                        float v   = acc[mt][nt][q] * 10.0f;
                        bool  self = diag && (col == row);
                        float e   = __expf(v);
                        if (!self) {
                            re[mt][q >> 1] += e;
                            if (li[mt][q >> 1] == lj) rp[mt][q >> 1] += v;
                        }
                    }
                }
            }
        }
        __syncthreads();   // protect buffer before next prefetch overwrite
    }

    // Quad reduction (lanes sharing lane>>2 hold the same 4 rows)
    #pragma unroll
    for (int mt = 0; mt < 2; mt++) {
        #pragma unroll
        for (int h = 0; h < 2; h++) {
            float s = re[mt][h];
            s += __shfl_xor_sync(0xffffffffu, s, 1);
            s += __shfl_xor_sync(0xffffffffu, s, 2);
            float p = rp[mt][h];
            p += __shfl_xor_sync(0xffffffffu, p, 1);
            p += __shfl_xor_sync(0xffffffffu, p, 2);
            if ((lane & 3) == 0) {
                int row = bi * TM + wid * 32 + mt * 16 + h * 8 + (lane >> 2);
                atomicAdd(&g_sumexp[row], s);
                atomicAdd(&g_possum[row], p);
            }
        }
    }
}

// ---------------------------------------------------------------------------
__global__ void finish_kernel(float* out) {
    __shared__ float red[256];
    int tid = threadIdx.x;
    float sum = 0.0f;
    for (int r = tid; r < NN; r += 256) {
        float L   = logf(g_sumexp[r] + 1e-9f);
        int   cnt = g_hist[g_lab[r] & 1023] - 1;
        float c   = (cnt > 0) ? (g_possum[r] - (float)cnt * L) / (float)cnt : 0.0f;
        sum += c;
    }
    red[tid] = sum;
    __syncthreads();
    for (int s = 128; s > 0; s >>= 1) {
        if (tid < s) red[tid] += red[tid + s];
        __syncthreads();
    }
    if (tid == 0) out[0] = -red[0] / (float)NN;
}

// ---------------------------------------------------------------------------
extern "C" void kernel_launch(void* const* d_in, const int* in_sizes, int n_in,
                              void* d_out, int out_size) {
    const float* feats  = (const float*)d_in[0];
    const void*  labels = d_in[1];
    float* out = (float*)d_out;

    cudaFuncSetAttribute(main_kernel,
                         cudaFuncAttributeMaxDynamicSharedMemorySize, SM_TOT);

    init_kernel<<<32, 256>>>(out);
    detect_kernel<<<1, 256>>>((const int*)labels);
    prep_kernel<<<NN / 8, 256>>>(feats, labels);
    main_kernel<<<NT * PARTS, 128, SM_TOT>>>();
    finish_kernel<<<1, 256>>>(out);
}

// round 11
// speedup vs baseline: 3.8327x; 1.3564x over previous
#include <cuda_runtime.h>
#include <cuda_bf16.h>
#include <cstdint>

// SupConLoss N=8192, D=128, T=0.1 — mma.sync bf16 tensor cores (sm_103 base
// target: no tcgen05). R9: 256-thread CTAs owning 256 rows, 64-col j-blocks,
// one-wave grid, occupancy 2x vs R8.

static constexpr int NN = 8192;
static constexpr int DD = 128;
static constexpr int MC = 256;            // rows per CTA
static constexpr int NJ = 64;             // cols per j-block
static constexpr int STRIPS = NN / MC;    // 32
static constexpr int PARTS  = 8;
static constexpr int JB_PER = (NN / NJ) / PARTS;  // 16

__device__ __align__(16) __nv_bfloat16 g_featbf[NN * DD];
__device__ float g_sumexp[NN];
__device__ float g_possum[NN];
__device__ int   g_lab[NN];
__device__ int   g_hist[1024];
__device__ int   g_is64;

// ---------------- PTX helpers (base-target only) -----------------------------
__device__ __forceinline__ uint32_t smem_u32(const void* p) {
    uint32_t a;
    asm("{ .reg .u64 t; cvta.to.shared.u64 t, %1; cvt.u32.u64 %0, t; }"
        : "=r"(a) : "l"(p));
    return a;
}
#define LDSM4(r0, r1, r2, r3, addr) \
    asm volatile("ldmatrix.sync.aligned.m8n8.x4.shared.b16 {%0,%1,%2,%3}, [%4];" \
        : "=r"(r0), "=r"(r1), "=r"(r2), "=r"(r3) : "r"(addr))
#define MMA16816(d, a0, a1, a2, a3, b0, b1) \
    asm volatile("mma.sync.aligned.m16n8k16.row.col.f32.bf16.bf16.f32 " \
        "{%0,%1,%2,%3}, {%4,%5,%6,%7}, {%8,%9}, {%0,%1,%2,%3};" \
        : "+f"((d)[0]), "+f"((d)[1]), "+f"((d)[2]), "+f"((d)[3]) \
        : "r"(a0), "r"(a1), "r"(a2), "r"(a3), "r"(b0), "r"(b1))
#define CP_ASYNC16(sdst, gsrc) \
    asm volatile("cp.async.cg.shared.global [%0], [%1], 16;" \
        :: "r"(sdst), "l"(gsrc) : "memory")
#define CP_COMMIT()  asm volatile("cp.async.commit_group;" ::: "memory")
#define CP_WAIT0()   asm volatile("cp.async.wait_group 0;" ::: "memory")
#define CP_WAIT1()   asm volatile("cp.async.wait_group 1;" ::: "memory")

// ---------------------------------------------------------------------------
// init + dtype-detect fused (block 0 does the scan).
__global__ void init_kernel(const int* __restrict__ labs, float* out) {
    int gid = blockIdx.x * 256 + threadIdx.x;
    if (gid < NN)   { g_sumexp[gid] = 0.0f; g_possum[gid] = 0.0f; }
    if (gid < 1024) g_hist[gid] = 0;
    if (gid == 0)   out[0] = 0.0f;
    if (blockIdx.x == 0) {
        __shared__ int red[256];
        int tid = threadIdx.x;
        int nz = 0;
        for (int i = tid; i < NN / 2; i += 256) nz |= labs[2 * i + 1];
        red[tid] = nz;
        __syncthreads();
        for (int s = 128; s > 0; s >>= 1) {
            if (tid < s) red[tid] |= red[tid + s];
            __syncthreads();
        }
        if (tid == 0) g_is64 = (red[0] == 0) ? 1 : 0;
    }
}

// Normalize rows, convert to bf16, label histogram.
__global__ void prep_kernel(const float* __restrict__ feats,
                            const void* __restrict__ labels) {
    int row  = blockIdx.x * 8 + (threadIdx.x >> 5);
    int lane = threadIdx.x & 31;
    float4 v = reinterpret_cast<const float4*>(feats)[row * 32 + lane];
    float ss = v.x * v.x + v.y * v.y + v.z * v.z + v.w * v.w;
    #pragma unroll
    for (int o = 16; o > 0; o >>= 1) ss += __shfl_xor_sync(0xffffffffu, ss, o);
    float sc = 1.0f / sqrtf(ss);
    __nv_bfloat162 p0 = __floats2bfloat162_rn(v.x * sc, v.y * sc);
    __nv_bfloat162 p1 = __floats2bfloat162_rn(v.z * sc, v.w * sc);
    uint2 u;
    u.x = *reinterpret_cast<uint32_t*>(&p0);
    u.y = *reinterpret_cast<uint32_t*>(&p1);
    reinterpret_cast<uint2*>(g_featbf)[row * 32 + lane] = u;
    if (lane == 0) {
        int lab = g_is64 ? (int)((const long long*)labels)[row]
                         : ((const int*)labels)[row];
        g_lab[row] = lab;
        atomicAdd(&g_hist[lab & 1023], 1);
    }
}

// ---------------------------------------------------------------------------
// SMEM: A 64KB (256 rows x 256B) | B half-tiles 2x16KB (64 rows) | labels.
// Row layout: 256B K-major, 16B chunks XOR-swizzled with (row & 7).
static constexpr int SM_A   = 0;
static constexpr int SM_B0  = 65536;
static constexpr int SM_B1  = 81920;
static constexpr int SM_LJ0 = 98304;
static constexpr int SM_LJ1 = 98560;
static constexpr int SM_TOT = 98816;

__device__ __forceinline__ void cp_tileA(uint32_t sdst,
                                         const __nv_bfloat16* gsrc, int tid) {
    #pragma unroll
    for (int i = 0; i < 16; i++) {
        int e   = i * 256 + tid;        // 4096 x 16B
        int row = e >> 4;
        int ch  = e & 15;
        uint32_t off = row * 256 + ((ch ^ (row & 7)) << 4);
        CP_ASYNC16(sdst + off, (const char*)gsrc + (size_t)e * 16);
    }
}
__device__ __forceinline__ void cp_tileB(uint32_t sdst,
                                         const __nv_bfloat16* gsrc, int tid) {
    #pragma unroll
    for (int i = 0; i < 4; i++) {
        int e   = i * 256 + tid;        // 1024 x 16B
        int row = e >> 4;
        int ch  = e & 15;
        uint32_t off = row * 256 + ((ch ^ (row & 7)) << 4);
        CP_ASYNC16(sdst + off, (const char*)gsrc + (size_t)e * 16);
    }
}

__global__ void __launch_bounds__(256, 2)
main_kernel() {
    extern __shared__ char smem[];
    uint32_t sb = smem_u32(smem);
    int tid  = threadIdx.x;
    int wid  = tid >> 5, lane = tid & 31;
    int sub  = lane & 7, g = lane >> 3;

    int strip = blockIdx.x >> 3;
    int part  = blockIdx.x & 7;
    int rbase = strip * MC;
    int jb0   = part * JB_PER;

    // Prefetch A (group spans both commits below; waited via WAIT1/WAIT0)
    cp_tileA(sb + SM_A, g_featbf + (size_t)rbase * DD, tid);
    cp_tileB(sb + SM_B0, g_featbf + (size_t)jb0 * NJ * DD, tid);
    if (tid < 16) CP_ASYNC16(sb + SM_LJ0 + tid * 16,
                             (const char*)(g_lab + jb0 * NJ) + tid * 16);
    CP_COMMIT();

    // Row labels (4 rows per lane: [mt][h])
    int li[2][2];
    #pragma unroll
    for (int mt = 0; mt < 2; mt++)
        #pragma unroll
        for (int h = 0; h < 2; h++)
            li[mt][h] = g_lab[rbase + wid * 32 + mt * 16 + h * 8 + (lane >> 2)];

    int arow = wid * 32 + (g & 1) * 8 + sub;   // + mt*16
    int akx  = g >> 1;
    int brow = (g >> 1) * 8 + sub;             // + p*16
    int bkx  = g & 1;

    float re[2][2] = {{0, 0}, {0, 0}};
    float rp[2][2] = {{0, 0}, {0, 0}};

    for (int it = 0; it < JB_PER; it++) {
        int jb = jb0 + it;
        if (it + 1 < JB_PER) {
            uint32_t nb = (it & 1) ? SM_B0 : SM_B1;
            uint32_t nl = (it & 1) ? SM_LJ0 : SM_LJ1;
            cp_tileB(sb + nb, g_featbf + (size_t)(jb + 1) * NJ * DD, tid);
            if (tid < 16) CP_ASYNC16(sb + nl + tid * 16,
                                     (const char*)(g_lab + (jb + 1) * NJ) + tid * 16);
            CP_COMMIT();
            CP_WAIT1();
        } else {
            CP_WAIT0();
        }
        __syncthreads();

        uint32_t SB = sb + ((it & 1) ? SM_B1 : SM_B0);
        const int* s_lj = reinterpret_cast<const int*>(
            smem + ((it & 1) ? SM_LJ1 : SM_LJ0));
        int jc0 = jb * NJ;
        int dsh = jc0 - rbase;   // self when col_local == row_local + ... see below

        float acc[2][8][4];
        #pragma unroll
        for (int mt = 0; mt < 2; mt++)
            #pragma unroll
            for (int nt = 0; nt < 8; nt++)
                #pragma unroll
                for (int q = 0; q < 4; q++) acc[mt][nt][q] = 0.0f;

        #pragma unroll
        for (int k = 0; k < 8; k++) {
            uint32_t a[2][4];
            #pragma unroll
            for (int mt = 0; mt < 2; mt++) {
                uint32_t addr = sb + SM_A + (arow + mt * 16) * 256
                              + (((k * 2 + akx) ^ sub) << 4);
                LDSM4(a[mt][0], a[mt][1], a[mt][2], a[mt][3], addr);
            }
            #pragma unroll
            for (int p = 0; p < 4; p++) {
                uint32_t b0, b1, b2, b3;
                uint32_t addr = SB + (p * 16 + brow) * 256
                              + (((k * 2 + bkx) ^ sub) << 4);
                LDSM4(b0, b1, b2, b3, addr);
                MMA16816(acc[0][2 * p],     a[0][0], a[0][1], a[0][2], a[0][3], b0, b1);
                MMA16816(acc[0][2 * p + 1], a[0][0], a[0][1], a[0][2], a[0][3], b2, b3);
                MMA16816(acc[1][2 * p],     a[1][0], a[1][1], a[1][2], a[1][3], b0, b1);
                MMA16816(acc[1][2 * p + 1], a[1][0], a[1][1], a[1][2], a[1][3], b2, b3);
            }
        }

        // Fused epilogue
        #pragma unroll
        for (int nt = 0; nt < 8; nt++) {
            int c0  = nt * 8 + 2 * (lane & 3);
            int lj0 = s_lj[c0], lj1 = s_lj[c0 + 1];
            #pragma unroll
            for (int mt = 0; mt < 2; mt++) {
                int r0 = wid * 32 + mt * 16 + (lane >> 2);
                #pragma unroll
                for (int q = 0; q < 4; q++) {
                    int   rl  = r0 + (q >> 1) * 8;
                    int   c   = c0 + (q & 1);
                    int   lj  = (q & 1) ? lj1 : lj0;
                    float v   = acc[mt][nt][q] * 10.0f;
                    bool  self = (c + dsh) == rl;   // global col == global row
                    float e   = __expf(v);
                    if (!self) {
                        re[mt][q >> 1] += e;
                        if (li[mt][q >> 1] == lj) rp[mt][q >> 1] += v;
                    }
                }
            }
        }
        __syncthreads();   // all reads done before next prefetch overwrites
    }

    // Quad reduction + one atomic pair per row
    #pragma unroll
    for (int mt = 0; mt < 2; mt++) {
        #pragma unroll
        for (int h = 0; h < 2; h++) {
            float s = re[mt][h];
            s += __shfl_xor_sync(0xffffffffu, s, 1);
            s += __shfl_xor_sync(0xffffffffu, s, 2);
            float p = rp[mt][h];
            p += __shfl_xor_sync(0xffffffffu, p, 1);
            p += __shfl_xor_sync(0xffffffffu, p, 2);
            if ((lane & 3) == 0) {
                int row = rbase + wid * 32 + mt * 16 + h * 8 + (lane >> 2);
                atomicAdd(&g_sumexp[row], s);
                atomicAdd(&g_possum[row], p);
            }
        }
    }
}

// ---------------------------------------------------------------------------
__global__ void finish_kernel(float* out) {
    __shared__ float red[1024];
    int tid = threadIdx.x;
    float sum = 0.0f;
    for (int r = tid; r < NN; r += 1024) {
        float L   = logf(g_sumexp[r] + 1e-9f);
        int   cnt = g_hist[g_lab[r] & 1023] - 1;
        float c   = (cnt > 0) ? (g_possum[r] - (float)cnt * L) / (float)cnt : 0.0f;
        sum += c;
    }
    red[tid] = sum;
    __syncthreads();
    for (int s = 512; s > 0; s >>= 1) {
        if (tid < s) red[tid] += red[tid + s];
        __syncthreads();
    }
    if (tid == 0) out[0] = -red[0] / (float)NN;
}

// ---------------------------------------------------------------------------
extern "C" void kernel_launch(void* const* d_in, const int* in_sizes, int n_in,
                              void* d_out, int out_size) {
    const float* feats  = (const float*)d_in[0];
    const void*  labels = d_in[1];
    float* out = (float*)d_out;

    cudaFuncSetAttribute(main_kernel,
                         cudaFuncAttributeMaxDynamicSharedMemorySize, SM_TOT);

    init_kernel<<<32, 256>>>((const int*)labels, out);
    prep_kernel<<<NN / 8, 256>>>(feats, labels);
    main_kernel<<<STRIPS * PARTS, 256, SM_TOT>>>();
    finish_kernel<<<1, 1024>>>(out);
}

// round 12
// speedup vs baseline: 4.3945x; 1.1466x over previous
#include <cuda_runtime.h>
#include <cuda_bf16.h>
#include <cstdint>

// SupConLoss N=8192, D=128, T=0.1 — mma.sync bf16 tensor cores (sm_103 base
// target: no tcgen05). R12: parallel finish, single-sync mainloop pipeline,
// leaner fused epilogue (const-folded ex2, DIAG-templated self-exclusion).

static constexpr int NN = 8192;
static constexpr int DD = 128;
static constexpr int MC = 256;            // rows per CTA
static constexpr int NJ = 64;             // cols per j-block
static constexpr int STRIPS = NN / MC;    // 32
static constexpr int PARTS  = 8;
static constexpr int JB_PER = (NN / NJ) / PARTS;  // 16

__device__ __align__(16) __nv_bfloat16 g_featbf[NN * DD];
__device__ float g_sumexp[NN];
__device__ float g_possum[NN];
__device__ int   g_lab[NN];
__device__ int   g_hist[1024];
__device__ int   g_is64;

// ---------------- PTX helpers (base-target only) -----------------------------
__device__ __forceinline__ uint32_t smem_u32(const void* p) {
    uint32_t a;
    asm("{ .reg .u64 t; cvta.to.shared.u64 t, %1; cvt.u32.u64 %0, t; }"
        : "=r"(a) : "l"(p));
    return a;
}
#define LDSM4(r0, r1, r2, r3, addr) \
    asm volatile("ldmatrix.sync.aligned.m8n8.x4.shared.b16 {%0,%1,%2,%3}, [%4];" \
        : "=r"(r0), "=r"(r1), "=r"(r2), "=r"(r3) : "r"(addr))
#define MMA16816(d, a0, a1, a2, a3, b0, b1) \
    asm volatile("mma.sync.aligned.m16n8k16.row.col.f32.bf16.bf16.f32 " \
        "{%0,%1,%2,%3}, {%4,%5,%6,%7}, {%8,%9}, {%0,%1,%2,%3};" \
        : "+f"((d)[0]), "+f"((d)[1]), "+f"((d)[2]), "+f"((d)[3]) \
        : "r"(a0), "r"(a1), "r"(a2), "r"(a3), "r"(b0), "r"(b1))
#define CP_ASYNC16(sdst, gsrc) \
    asm volatile("cp.async.cg.shared.global [%0], [%1], 16;" \
        :: "r"(sdst), "l"(gsrc) : "memory")
#define CP_COMMIT()  asm volatile("cp.async.commit_group;" ::: "memory")
#define CP_WAIT0()   asm volatile("cp.async.wait_group 0;" ::: "memory")

// ---------------------------------------------------------------------------
__global__ void init_kernel(const int* __restrict__ labs, float* out) {
    int gid = blockIdx.x * 256 + threadIdx.x;
    if (gid < NN)   { g_sumexp[gid] = 0.0f; g_possum[gid] = 0.0f; }
    if (gid < 1024) g_hist[gid] = 0;
    if (gid == 0)   out[0] = 0.0f;
    if (blockIdx.x == 0) {
        __shared__ int red[256];
        int tid = threadIdx.x;
        int nz = 0;
        for (int i = tid; i < NN / 2; i += 256) nz |= labs[2 * i + 1];
        red[tid] = nz;
        __syncthreads();
        for (int s = 128; s > 0; s >>= 1) {
            if (tid < s) red[tid] |= red[tid + s];
            __syncthreads();
        }
        if (tid == 0) g_is64 = (red[0] == 0) ? 1 : 0;
    }
}

__global__ void prep_kernel(const float* __restrict__ feats,
                            const void* __restrict__ labels) {
    int row  = blockIdx.x * 8 + (threadIdx.x >> 5);
    int lane = threadIdx.x & 31;
    float4 v = reinterpret_cast<const float4*>(feats)[row * 32 + lane];
    float ss = v.x * v.x + v.y * v.y + v.z * v.z + v.w * v.w;
    #pragma unroll
    for (int o = 16; o > 0; o >>= 1) ss += __shfl_xor_sync(0xffffffffu, ss, o);
    float sc = 1.0f / sqrtf(ss);
    __nv_bfloat162 p0 = __floats2bfloat162_rn(v.x * sc, v.y * sc);
    __nv_bfloat162 p1 = __floats2bfloat162_rn(v.z * sc, v.w * sc);
    uint2 u;
    u.x = *reinterpret_cast<uint32_t*>(&p0);
    u.y = *reinterpret_cast<uint32_t*>(&p1);
    reinterpret_cast<uint2*>(g_featbf)[row * 32 + lane] = u;
    if (lane == 0) {
        int lab = g_is64 ? (int)((const long long*)labels)[row]
                         : ((const int*)labels)[row];
        g_lab[row] = lab;
        atomicAdd(&g_hist[lab & 1023], 1);
    }
}

// ---------------------------------------------------------------------------
// SMEM: A 64KB (256 rows x 256B) | B half-tiles 2x16KB | labels 2x256B.
// Rows: 256B K-major, 16B chunks XOR-swizzled with (row & 7).
static constexpr int SM_A   = 0;
static constexpr int SM_B0  = 65536;
static constexpr int SM_B1  = 81920;
static constexpr int SM_LJ0 = 98304;
static constexpr int SM_LJ1 = 98560;
static constexpr int SM_TOT = 98816;

__device__ __forceinline__ void cp_tileA(uint32_t sdst,
                                         const __nv_bfloat16* gsrc, int tid) {
    #pragma unroll
    for (int i = 0; i < 16; i++) {
        int e   = i * 256 + tid;
        int row = e >> 4;
        int ch  = e & 15;
        uint32_t off = row * 256 + ((ch ^ (row & 7)) << 4);
        CP_ASYNC16(sdst + off, (const char*)gsrc + (size_t)e * 16);
    }
}
__device__ __forceinline__ void cp_tileB(uint32_t sdst,
                                         const __nv_bfloat16* gsrc, int tid) {
    #pragma unroll
    for (int i = 0; i < 4; i++) {
        int e   = i * 256 + tid;
        int row = e >> 4;
        int ch  = e & 15;
        uint32_t off = row * 256 + ((ch ^ (row & 7)) << 4);
        CP_ASYNC16(sdst + off, (const char*)gsrc + (size_t)e * 16);
    }
}

// exp(10*x) = ex2(x * 10*log2(e))
static constexpr float EXSCALE = 14.4269504088896341f;

template <bool DIAG>
__device__ __forceinline__ void epilogue(const float (&acc)[2][8][4],
                                         const int* __restrict__ s_lj, int dsh,
                                         int wid, int lane,
                                         const int (&li)[2][2],
                                         float (&re)[2][2], float (&rp)[2][2]) {
    #pragma unroll
    for (int nt = 0; nt < 8; nt++) {
        int c0  = nt * 8 + 2 * (lane & 3);
        int lj0 = s_lj[c0], lj1 = s_lj[c0 + 1];
        #pragma unroll
        for (int mt = 0; mt < 2; mt++) {
            int r0 = wid * 32 + mt * 16 + (lane >> 2);
            #pragma unroll
            for (int q = 0; q < 4; q++) {
                int   rl = r0 + (q >> 1) * 8;
                int   c  = c0 + (q & 1);
                int   lj = (q & 1) ? lj1 : lj0;
                float a  = acc[mt][nt][q];
                float x  = a * EXSCALE;
                float e;
                asm("ex2.approx.f32 %0, %1;" : "=f"(e) : "f"(x));
                bool self = DIAG && ((c + dsh) == rl);
                if (!self) {
                    re[mt][q >> 1] += e;
                    if (li[mt][q >> 1] == lj) rp[mt][q >> 1] += a;
                }
            }
        }
    }
}

__global__ void __launch_bounds__(256, 2)
main_kernel() {
    extern __shared__ char smem[];
    uint32_t sb = smem_u32(smem);
    int tid  = threadIdx.x;
    int wid  = tid >> 5, lane = tid & 31;
    int sub  = lane & 7, g = lane >> 3;

    int strip = blockIdx.x >> 3;
    int part  = blockIdx.x & 7;
    int rbase = strip * MC;
    int jb0   = part * JB_PER;

    // Prefetch A + B0 + labels0 as group 0.
    cp_tileA(sb + SM_A, g_featbf + (size_t)rbase * DD, tid);
    cp_tileB(sb + SM_B0, g_featbf + (size_t)jb0 * NJ * DD, tid);
    if (tid < 16) CP_ASYNC16(sb + SM_LJ0 + tid * 16,
                             (const char*)(g_lab + jb0 * NJ) + tid * 16);
    CP_COMMIT();

    int li[2][2];
    #pragma unroll
    for (int mt = 0; mt < 2; mt++)
        #pragma unroll
        for (int h = 0; h < 2; h++)
            li[mt][h] = g_lab[rbase + wid * 32 + mt * 16 + h * 8 + (lane >> 2)];

    int arow = wid * 32 + (g & 1) * 8 + sub;
    int akx  = g >> 1;
    int brow = (g >> 1) * 8 + sub;
    int bkx  = g & 1;

    float re[2][2] = {{0, 0}, {0, 0}};
    float rp[2][2] = {{0, 0}, {0, 0}};

    for (int it = 0; it < JB_PER; it++) {
        int jb = jb0 + it;

        // wait current buffer -> sync -> THEN prefetch next (single-sync
        // pipeline: buf[(it+1)&1] was last read at it-1, and every thread
        // passed this barrier after finishing it-1, so overwrite is safe).
        CP_WAIT0();
        __syncthreads();
        if (it + 1 < JB_PER) {
            uint32_t nb = (it & 1) ? SM_B0 : SM_B1;
            uint32_t nl = (it & 1) ? SM_LJ0 : SM_LJ1;
            cp_tileB(sb + nb, g_featbf + (size_t)(jb + 1) * NJ * DD, tid);
            if (tid < 16) CP_ASYNC16(sb + nl + tid * 16,
                                     (const char*)(g_lab + (jb + 1) * NJ) + tid * 16);
            CP_COMMIT();
        }

        uint32_t SB = sb + ((it & 1) ? SM_B1 : SM_B0);
        const int* s_lj = reinterpret_cast<const int*>(
            smem + ((it & 1) ? SM_LJ1 : SM_LJ0));
        int dsh = jb * NJ - rbase;

        float acc[2][8][4];
        #pragma unroll
        for (int mt = 0; mt < 2; mt++)
            #pragma unroll
            for (int nt = 0; nt < 8; nt++)
                #pragma unroll
                for (int q = 0; q < 4; q++) acc[mt][nt][q] = 0.0f;

        #pragma unroll
        for (int k = 0; k < 8; k++) {
            uint32_t a[2][4];
            #pragma unroll
            for (int mt = 0; mt < 2; mt++) {
                uint32_t addr = sb + SM_A + (arow + mt * 16) * 256
                              + (((k * 2 + akx) ^ sub) << 4);
                LDSM4(a[mt][0], a[mt][1], a[mt][2], a[mt][3], addr);
            }
            #pragma unroll
            for (int p = 0; p < 4; p++) {
                uint32_t b0, b1, b2, b3;
                uint32_t addr = SB + (p * 16 + brow) * 256
                              + (((k * 2 + bkx) ^ sub) << 4);
                LDSM4(b0, b1, b2, b3, addr);
                MMA16816(acc[0][2 * p],     a[0][0], a[0][1], a[0][2], a[0][3], b0, b1);
                MMA16816(acc[0][2 * p + 1], a[0][0], a[0][1], a[0][2], a[0][3], b2, b3);
                MMA16816(acc[1][2 * p],     a[1][0], a[1][1], a[1][2], a[1][3], b0, b1);
                MMA16816(acc[1][2 * p + 1], a[1][0], a[1][1], a[1][2], a[1][3], b2, b3);
            }
        }

        // diag block only when this 64-col window intersects the CTA's rows
        if (dsh >= -(NJ - 1) && dsh <= MC - 1)
            epilogue<true>(acc, s_lj, dsh, wid, lane, li, re, rp);
        else
            epilogue<false>(acc, s_lj, dsh, wid, lane, li, re, rp);
    }

    // Quad reduction + one atomic pair per row (possum scaled by 1/T here).
    #pragma unroll
    for (int mt = 0; mt < 2; mt++) {
        #pragma unroll
        for (int h = 0; h < 2; h++) {
            float s = re[mt][h];
            s += __shfl_xor_sync(0xffffffffu, s, 1);
            s += __shfl_xor_sync(0xffffffffu, s, 2);
            float p = rp[mt][h];
            p += __shfl_xor_sync(0xffffffffu, p, 1);
            p += __shfl_xor_sync(0xffffffffu, p, 2);
            if ((lane & 3) == 0) {
                int row = rbase + wid * 32 + mt * 16 + h * 8 + (lane >> 2);
                atomicAdd(&g_sumexp[row], s);
                atomicAdd(&g_possum[row], p * 10.0f);
            }
        }
    }
}

// ---------------------------------------------------------------------------
// Parallel finish: one row per thread, block partial sums, atomic combine.
__global__ void finish_kernel(float* out) {
    __shared__ float red[256];
    int tid = threadIdx.x;
    int r   = blockIdx.x * 256 + tid;
    float L   = logf(g_sumexp[r] + 1e-9f);
    int   cnt = g_hist[g_lab[r] & 1023] - 1;
    float c   = (cnt > 0) ? (g_possum[r] - (float)cnt * L) / (float)cnt : 0.0f;
    // warp reduce then block reduce
    #pragma unroll
    for (int o = 16; o > 0; o >>= 1) c += __shfl_xor_sync(0xffffffffu, c, o);
    if ((tid & 31) == 0) red[tid >> 5] = c;
    __syncthreads();
    if (tid < 8) {
        float s = red[tid];
        #pragma unroll
        for (int o = 4; o > 0; o >>= 1) s += __shfl_xor_sync(0xffu, s, o);
        if (tid == 0) atomicAdd(out, -s / (float)NN);
    }
}

// ---------------------------------------------------------------------------
extern "C" void kernel_launch(void* const* d_in, const int* in_sizes, int n_in,
                              void* d_out, int out_size) {
    const float* feats  = (const float*)d_in[0];
    const void*  labels = d_in[1];
    float* out = (float*)d_out;

    cudaFuncSetAttribute(main_kernel,
                         cudaFuncAttributeMaxDynamicSharedMemorySize, SM_TOT);

    init_kernel<<<32, 256>>>((const int*)labels, out);
    prep_kernel<<<NN / 8, 256>>>(feats, labels);
    main_kernel<<<STRIPS * PARTS, 256, SM_TOT>>>();
    finish_kernel<<<NN / 256, 256>>>(out);
}

// round 14
// speedup vs baseline: 5.3230x; 1.2113x over previous
#include <cuda_runtime.h>
#include <cuda_bf16.h>
#include <cstdint>

// SupConLoss N=8192, D=128, T=0.1 — mma.sync bf16 (sm_103 base target).
// R13: SYMMETRIC tiling. 2080 CTAs, one 128x128 tile of the upper triangle
// each; every tile feeds row-side (bi) and col-side (bj) accumulators, so
// HMMA + exp work is halved vs R12.

static constexpr int NN = 8192;
static constexpr int DD = 128;
static constexpr int TB = 128;            // tile dim
static constexpr int NT = NN / TB;        // 64
static constexpr int NTILES = NT * (NT / 2) + NT / 2; // 2080 (d=0..31 all bi, d=32 half)

__device__ __align__(16) __nv_bfloat16 g_featbf[NN * DD];
__device__ float g_sumexp[NN];
__device__ float g_possum[NN];
__device__ int   g_lab[NN];
__device__ int   g_hist[1024];
__device__ int   g_is64;

// ---------------- PTX helpers (base-target only) -----------------------------
__device__ __forceinline__ uint32_t smem_u32(const void* p) {
    uint32_t a;
    asm("{ .reg .u64 t; cvta.to.shared.u64 t, %1; cvt.u32.u64 %0, t; }"
        : "=r"(a) : "l"(p));
    return a;
}
#define LDSM4(r0, r1, r2, r3, addr) \
    asm volatile("ldmatrix.sync.aligned.m8n8.x4.shared.b16 {%0,%1,%2,%3}, [%4];" \
        : "=r"(r0), "=r"(r1), "=r"(r2), "=r"(r3) : "r"(addr))
#define MMA16816(d, a0, a1, a2, a3, b0, b1) \
    asm volatile("mma.sync.aligned.m16n8k16.row.col.f32.bf16.bf16.f32 " \
        "{%0,%1,%2,%3}, {%4,%5,%6,%7}, {%8,%9}, {%0,%1,%2,%3};" \
        : "+f"((d)[0]), "+f"((d)[1]), "+f"((d)[2]), "+f"((d)[3]) \
        : "r"(a0), "r"(a1), "r"(a2), "r"(a3), "r"(b0), "r"(b1))
#define CP_ASYNC16(sdst, gsrc) \
    asm volatile("cp.async.cg.shared.global [%0], [%1], 16;" \
        :: "r"(sdst), "l"(gsrc) : "memory")
#define CP_COMMIT()  asm volatile("cp.async.commit_group;" ::: "memory")
#define CP_WAIT0()   asm volatile("cp.async.wait_group 0;" ::: "memory")

// ---------------------------------------------------------------------------
__global__ void init_kernel(const int* __restrict__ labs, float* out) {
    int gid = blockIdx.x * 256 + threadIdx.x;
    if (gid < NN)   { g_sumexp[gid] = 0.0f; g_possum[gid] = 0.0f; }
    if (gid < 1024) g_hist[gid] = 0;
    if (gid == 0)   out[0] = 0.0f;
    if (blockIdx.x == 0) {
        __shared__ int red[256];
        int tid = threadIdx.x;
        int nz = 0;
        for (int i = tid; i < NN / 2; i += 256) nz |= labs[2 * i + 1];
        red[tid] = nz;
        __syncthreads();
        for (int s = 128; s > 0; s >>= 1) {
            if (tid < s) red[tid] |= red[tid + s];
            __syncthreads();
        }
        if (tid == 0) g_is64 = (red[0] == 0) ? 1 : 0;
    }
}

__global__ void prep_kernel(const float* __restrict__ feats,
                            const void* __restrict__ labels) {
    int row  = blockIdx.x * 8 + (threadIdx.x >> 5);
    int lane = threadIdx.x & 31;
    float4 v = reinterpret_cast<const float4*>(feats)[row * 32 + lane];
    float ss = v.x * v.x + v.y * v.y + v.z * v.z + v.w * v.w;
    #pragma unroll
    for (int o = 16; o > 0; o >>= 1) ss += __shfl_xor_sync(0xffffffffu, ss, o);
    float sc = 1.0f / sqrtf(ss);
    __nv_bfloat162 p0 = __floats2bfloat162_rn(v.x * sc, v.y * sc);
    __nv_bfloat162 p1 = __floats2bfloat162_rn(v.z * sc, v.w * sc);
    uint2 u;
    u.x = *reinterpret_cast<uint32_t*>(&p0);
    u.y = *reinterpret_cast<uint32_t*>(&p1);
    reinterpret_cast<uint2*>(g_featbf)[row * 32 + lane] = u;
    if (lane == 0) {
        int lab = g_is64 ? (int)((const long long*)labels)[row]
                         : ((const int*)labels)[row];
        g_lab[row] = lab;
        atomicAdd(&g_hist[lab & 1023], 1);
    }
}

// ---------------------------------------------------------------------------
// SMEM: A 32KB | B 32KB | col labels 512B | col accumulators 2x512B.
// Rows: 256B K-major, 16B chunks XOR-swizzled with (row & 7).
static constexpr int SM_A   = 0;
static constexpr int SM_B   = 32768;
static constexpr int SM_LJ  = 65536;
static constexpr int SM_CE  = 66048;
static constexpr int SM_CP  = 66560;
static constexpr int SM_TOT = 67072;

__device__ __forceinline__ void cp_tile(uint32_t sdst,
                                        const __nv_bfloat16* gsrc, int tid) {
    #pragma unroll
    for (int i = 0; i < 8; i++) {
        int e   = i * 256 + tid;        // 2048 x 16B
        int row = e >> 4;
        int ch  = e & 15;
        uint32_t off = row * 256 + ((ch ^ (row & 7)) << 4);
        CP_ASYNC16(sdst + off, (const char*)gsrc + (size_t)e * 16);
    }
}

// exp(10*x) = ex2(x * 10*log2(e))
static constexpr float EXSCALE = 14.4269504088896341f;

template <bool DIAG>
__device__ __forceinline__ void epilogue(const float (&acc)[2][8][4],
                                         const int* __restrict__ s_lj,
                                         float* __restrict__ s_ce,
                                         float* __restrict__ s_cp,
                                         int wm, int wn, int lane,
                                         const int (&li)[2][2],
                                         float (&re)[2][2], float (&rp)[2][2]) {
    #pragma unroll
    for (int nt = 0; nt < 8; nt++) {
        int c0  = wn * 64 + nt * 8 + 2 * (lane & 3);
        int lj0 = s_lj[c0], lj1 = s_lj[c0 + 1];
        float ce0 = 0, ce1 = 0, cq0 = 0, cq1 = 0;
        #pragma unroll
        for (int mt = 0; mt < 2; mt++) {
            int r0 = wm * 32 + mt * 16 + (lane >> 2);
            #pragma unroll
            for (int q = 0; q < 4; q++) {
                int   h  = q >> 1;
                float a  = acc[mt][nt][q];
                float x  = a * EXSCALE;
                float e;
                asm("ex2.approx.f32 %0, %1;" : "=f"(e) : "f"(x));
                bool match = (li[mt][h] == ((q & 1) ? lj1 : lj0));
                if (DIAG) {
                    // self-pair exclusion (tile is on the diagonal)
                    int rl = r0 + h * 8;
                    if (c0 + (q & 1) == rl) { e = 0.0f; match = false; }
                }
                re[mt][h] += e;
                if (match) rp[mt][h] += a;
                if (!DIAG) {
                    if (q & 1) { ce1 += e; if (match) cq1 += a; }
                    else       { ce0 += e; if (match) cq0 += a; }
                }
            }
        }
        if (!DIAG) {
            // reduce over the 8 row-groups (lane>>2); lane&3 partition is kept
            #pragma unroll
            for (int o = 4; o <= 16; o <<= 1) {
                ce0 += __shfl_xor_sync(0xffffffffu, ce0, o);
                ce1 += __shfl_xor_sync(0xffffffffu, ce1, o);
                cq0 += __shfl_xor_sync(0xffffffffu, cq0, o);
                cq1 += __shfl_xor_sync(0xffffffffu, cq1, o);
            }
            if (lane < 4) {
                int c = wn * 64 + nt * 8 + 2 * lane;
                atomicAdd(&s_ce[c],     ce0);
                atomicAdd(&s_ce[c + 1], ce1);
                atomicAdd(&s_cp[c],     cq0);
                atomicAdd(&s_cp[c + 1], cq1);
            }
        }
    }
}

__global__ void __launch_bounds__(256, 2)
main_kernel() {
    extern __shared__ char smem[];
    uint32_t sb = smem_u32(smem);
    int tid  = threadIdx.x;
    int wid  = tid >> 5, lane = tid & 31;
    int sub  = lane & 7, g = lane >> 3;
    int wm   = wid & 3, wn = wid >> 2;     // 4x2 warp grid (M x N)

    // tile (bi, bj): d=0..31 for all bi, d=32 for bi<32 (upper triangle, once)
    int idx = blockIdx.x;
    int bi, d;
    if (idx < NT * 32) { bi = idx & (NT - 1); d = idx >> 6; }
    else               { bi = idx - NT * 32; d = 32; }
    int bj = (bi + d) & (NT - 1);
    bool diag = (d == 0);

    cp_tile(sb + SM_A, g_featbf + (size_t)bi * TB * DD, tid);
    if (!diag) cp_tile(sb + SM_B, g_featbf + (size_t)bj * TB * DD, tid);
    if (tid < 32) CP_ASYNC16(sb + SM_LJ + tid * 16,
                             (const char*)(g_lab + bj * TB) + tid * 16);
    CP_COMMIT();

    float* s_ce = reinterpret_cast<float*>(smem + SM_CE);
    float* s_cp = reinterpret_cast<float*>(smem + SM_CP);
    if (tid < 128) { s_ce[tid] = 0.0f; s_cp[tid] = 0.0f; }

    int li[2][2];
    #pragma unroll
    for (int mt = 0; mt < 2; mt++)
        #pragma unroll
        for (int h = 0; h < 2; h++)
            li[mt][h] = g_lab[bi * TB + wm * 32 + mt * 16 + h * 8 + (lane >> 2)];

    int arow = wm * 32 + (g & 1) * 8 + sub;          // + mt*16
    int akx  = g >> 1;
    int brow = wn * 64 + (g >> 1) * 8 + sub;         // + p*16
    int bkx  = g & 1;

    CP_WAIT0();
    __syncthreads();

    uint32_t SA = sb + SM_A;
    uint32_t SB = diag ? SA : (sb + SM_B);
    const int* s_lj = reinterpret_cast<const int*>(smem + SM_LJ);

    float acc[2][8][4];
    #pragma unroll
    for (int mt = 0; mt < 2; mt++)
        #pragma unroll
        for (int nt = 0; nt < 8; nt++)
            #pragma unroll
            for (int q = 0; q < 4; q++) acc[mt][nt][q] = 0.0f;

    #pragma unroll
    for (int k = 0; k < 8; k++) {
        uint32_t a[2][4];
        #pragma unroll
        for (int mt = 0; mt < 2; mt++) {
            uint32_t addr = SA + (arow + mt * 16) * 256
                          + (((k * 2 + akx) ^ sub) << 4);
            LDSM4(a[mt][0], a[mt][1], a[mt][2], a[mt][3], addr);
        }
        #pragma unroll
        for (int p = 0; p < 4; p++) {
            uint32_t b0, b1, b2, b3;
            uint32_t addr = SB + (brow + p * 16) * 256
                          + (((k * 2 + bkx) ^ sub) << 4);
            LDSM4(b0, b1, b2, b3, addr);
            MMA16816(acc[0][2 * p],     a[0][0], a[0][1], a[0][2], a[0][3], b0, b1);
            MMA16816(acc[0][2 * p + 1], a[0][0], a[0][1], a[0][2], a[0][3], b2, b3);
            MMA16816(acc[1][2 * p],     a[1][0], a[1][1], a[1][2], a[1][3], b0, b1);
            MMA16816(acc[1][2 * p + 1], a[1][0], a[1][1], a[1][2], a[1][3], b2, b3);
        }
    }

    float re[2][2] = {{0, 0}, {0, 0}};
    float rp[2][2] = {{0, 0}, {0, 0}};
    if (diag)
        epilogue<true >(acc, s_lj, s_ce, s_cp, wm, wn, lane, li, re, rp);
    else
        epilogue<false>(acc, s_lj, s_ce, s_cp, wm, wn, lane, li, re, rp);

    // Row side: quad reduce, one atomic pair per row per CTA.
    #pragma unroll
    for (int mt = 0; mt < 2; mt++) {
        #pragma unroll
        for (int h = 0; h < 2; h++) {
            float s = re[mt][h];
            s += __shfl_xor_sync(0xffffffffu, s, 1);
            s += __shfl_xor_sync(0xffffffffu, s, 2);
            float p = rp[mt][h];
            p += __shfl_xor_sync(0xffffffffu, p, 1);
            p += __shfl_xor_sync(0xffffffffu, p, 2);
            if ((lane & 3) == 0) {
                int row = bi * TB + wm * 32 + mt * 16 + h * 8 + (lane >> 2);
                atomicAdd(&g_sumexp[row], s);
                atomicAdd(&g_possum[row], p * 10.0f);
            }
        }
    }

    // Col side: flush smem accumulators to bj's rows (off-diagonal only).
    if (!diag) {
        __syncthreads();
        if (tid < 128) {
            atomicAdd(&g_sumexp[bj * TB + tid], s_ce[tid]);
            atomicAdd(&g_possum[bj * TB + tid], s_cp[tid] * 10.0f);
        }
    }
}

// ---------------------------------------------------------------------------
__global__ void finish_kernel(float* out) {
    __shared__ float red[256];
    int tid = threadIdx.x;
    int r   = blockIdx.x * 256 + tid;
    float L   = logf(g_sumexp[r] + 1e-9f);
    int   cnt = g_hist[g_lab[r] & 1023] - 1;
    float c   = (cnt > 0) ? (g_possum[r] - (float)cnt * L) / (float)cnt : 0.0f;
    #pragma unroll
    for (int o = 16; o > 0; o >>= 1) c += __shfl_xor_sync(0xffffffffu, c, o);
    if ((tid & 31) == 0) red[tid >> 5] = c;
    __syncthreads();
    if (tid < 8) {
        float s = red[tid];
        #pragma unroll
        for (int o = 4; o > 0; o >>= 1) s += __shfl_xor_sync(0xffu, s, o);
        if (tid == 0) atomicAdd(out, -s / (float)NN);
    }
}

// ---------------------------------------------------------------------------
extern "C" void kernel_launch(void* const* d_in, const int* in_sizes, int n_in,
                              void* d_out, int out_size) {
    const float* feats  = (const float*)d_in[0];
    const void*  labels = d_in[1];
    float* out = (float*)d_out;

    cudaFuncSetAttribute(main_kernel,
                         cudaFuncAttributeMaxDynamicSharedMemorySize, SM_TOT);

    init_kernel<<<32, 256>>>((const int*)labels, out);
    prep_kernel<<<NN / 8, 256>>>(feats, labels);
    main_kernel<<<NTILES, 256, SM_TOT>>>();
    finish_kernel<<<NN / 256, 256>>>(out);
}